// round 1
// baseline (speedup 1.0000x reference)
#include <cuda_runtime.h>

// Problem constants (fixed by the dataset)
#define NN 100000
#define EE 1600000
#define HD 128          // hidden = F_IN = 128
#define NC 8
#define EPS_BN 1e-5f
#define SLOPE 0.01f

// Scratch (device globals: allocation-free per the harness rules)
__device__ float g_A[(size_t)NN * HD];     // aggregation buffer
__device__ float g_B[(size_t)NN * HD];     // hidden activations
__device__ float g_outnorm[NN];
__device__ float g_innorm[NN];
__device__ float g_degs[NN];
__device__ float g_degd[NN];
__device__ float g_stats[2 * HD];          // col sums, col sums of squares

// ---------------------------------------------------------------------------
__global__ void zero_deg_kernel(float* degs, float* degd) {
    int i = blockIdx.x * blockDim.x + threadIdx.x;
    if (i < NN) { degs[i] = 0.f; degd[i] = 0.f; }
}

__global__ void zero_stats_kernel(float* stats) {
    int i = threadIdx.x;
    if (i < 2 * HD) stats[i] = 0.f;
}

__global__ void zero_agg_kernel(float4* a) {
    int i = blockIdx.x * blockDim.x + threadIdx.x;
    const int n4 = NN * (HD / 4);
    if (i < n4) a[i] = make_float4(0.f, 0.f, 0.f, 0.f);
}

__global__ void deg_kernel(const int* __restrict__ src, const int* __restrict__ dst,
                           float* degs, float* degd) {
    int e = blockIdx.x * blockDim.x + threadIdx.x;
    if (e >= EE) return;
    atomicAdd(&degs[src[e]], 1.f);
    atomicAdd(&degd[dst[e]], 1.f);
}

__global__ void norm_kernel(const float* __restrict__ degs, const float* __restrict__ degd,
                            float* outnorm, float* innorm) {
    int i = blockIdx.x * blockDim.x + threadIdx.x;
    if (i >= NN) return;
    outnorm[i] = rsqrtf(fmaxf(degs[i], 1.f));
    innorm[i]  = rsqrtf(fmaxf(degd[i], 1.f));
}

// Gather x[src]*out_norm[src], scatter-add into agg[dst]. One warp per edge,
// each lane handles a float4 chunk (128 floats = 32 lanes * float4).
__global__ void scatter_kernel(const float* __restrict__ x,
                               const int* __restrict__ src,
                               const int* __restrict__ dst,
                               const float* __restrict__ outnorm,
                               float* __restrict__ agg) {
    long long gid = (long long)blockIdx.x * blockDim.x + threadIdx.x;
    int e = (int)(gid >> 5);
    if (e >= EE) return;
    int lane = (int)(gid & 31);
    int s = src[e], d = dst[e];
    float4 v = ((const float4*)(x + (size_t)s * HD))[lane];
    float sc = outnorm[s];
    v.x *= sc; v.y *= sc; v.z *= sc; v.w *= sc;
    float* addr = agg + (size_t)d * HD + lane * 4;
    asm volatile("red.global.add.v4.f32 [%0], {%1,%2,%3,%4};"
                 :: "l"(addr), "f"(v.x), "f"(v.y), "f"(v.z), "f"(v.w) : "memory");
}

// out[row] = (agg[row] * innorm[row]) @ W + b ; optional fused LeakyReLU.
// Block: 256 threads, 64 rows per block, full W (128x128) + A-tile in smem.
__global__ void gemm_kernel(const float* __restrict__ A,
                            const float* __restrict__ innorm,
                            const float* __restrict__ W,
                            const float* __restrict__ b,
                            float* __restrict__ out, int act) {
    extern __shared__ float sm[];
    float* Ws = sm;               // 128*128
    float* As = sm + HD * HD;     // 64*128
    int tid = threadIdx.x;
    int block_row = blockIdx.x * 64;

    // load W (row-major [k][j])
    {
        float4* Wsv = (float4*)Ws;
        const float4* Wv = (const float4*)W;
        #pragma unroll
        for (int i = tid; i < HD * (HD / 4); i += 256) Wsv[i] = Wv[i];
    }
    // load A tile, pre-scaled by innorm
    for (int i = tid; i < 64 * (HD / 4); i += 256) {
        int r = i >> 5, c4 = i & 31;
        int row = block_row + r;
        float4 v = make_float4(0.f, 0.f, 0.f, 0.f);
        if (row < NN) {
            v = ((const float4*)(A + (size_t)row * HD))[c4];
            float s = innorm[row];
            v.x *= s; v.y *= s; v.z *= s; v.w *= s;
        }
        ((float4*)(As + r * HD))[c4] = v;
    }
    __syncthreads();

    int tx = tid & 31;        // 32 col-groups of 4
    int ty = tid >> 5;        // 8 row-groups of 8
    float acc[8][4];
    float4 bb = ((const float4*)b)[tx];
    #pragma unroll
    for (int r = 0; r < 8; r++) { acc[r][0] = bb.x; acc[r][1] = bb.y; acc[r][2] = bb.z; acc[r][3] = bb.w; }

    const float* Arow = As + ty * 8 * HD;
    #pragma unroll 4
    for (int k = 0; k < HD; k++) {
        float4 w = ((const float4*)(Ws + k * HD))[tx];
        #pragma unroll
        for (int r = 0; r < 8; r++) {
            float a = Arow[r * HD + k];
            acc[r][0] += a * w.x; acc[r][1] += a * w.y;
            acc[r][2] += a * w.z; acc[r][3] += a * w.w;
        }
    }
    #pragma unroll
    for (int r = 0; r < 8; r++) {
        int row = block_row + ty * 8 + r;
        if (row >= NN) continue;
        float4 o = make_float4(acc[r][0], acc[r][1], acc[r][2], acc[r][3]);
        if (act) {
            o.x = o.x >= 0.f ? o.x : SLOPE * o.x;
            o.y = o.y >= 0.f ? o.y : SLOPE * o.y;
            o.z = o.z >= 0.f ? o.z : SLOPE * o.z;
            o.w = o.w >= 0.f ? o.w : SLOPE * o.w;
        }
        ((float4*)(out + (size_t)row * HD))[tx] = o;
    }
}

// Column sums + sums of squares (for BN batch stats).
__global__ void stats_kernel(const float* __restrict__ x, float* __restrict__ stats) {
    int col = threadIdx.x & (HD - 1);
    int half = threadIdx.x >> 7;                 // 2 row-streams per block
    float s = 0.f, s2 = 0.f;
    for (int row = blockIdx.x * 2 + half; row < NN; row += gridDim.x * 2) {
        float v = x[(size_t)row * HD + col];
        s += v; s2 += v * v;
    }
    __shared__ float sh[256], sh2[256];
    sh[threadIdx.x] = s; sh2[threadIdx.x] = s2;
    __syncthreads();
    if (half == 0) {
        atomicAdd(&stats[col],      sh[col] + sh[col + 128]);
        atomicAdd(&stats[HD + col], sh2[col] + sh2[col + 128]);
    }
}

// BN (training-mode, biased var) + LeakyReLU, in place.
__global__ void bn_apply_kernel(float* __restrict__ x,
                                const float* __restrict__ gamma,
                                const float* __restrict__ beta,
                                const float* __restrict__ stats) {
    long long i = (long long)blockIdx.x * blockDim.x + threadIdx.x;
    const long long total = (long long)NN * HD;
    if (i >= total) return;
    int col = (int)(i & (HD - 1));
    float mean = stats[col] * (1.f / NN);
    float var = stats[HD + col] * (1.f / NN) - mean * mean;
    float rstd = rsqrtf(var + EPS_BN);
    float v = (x[i] - mean) * rstd * gamma[col] + beta[col];
    x[i] = v >= 0.f ? v : SLOPE * v;
}

// Final classifier: out[N,8] = h @ Wc + bc. Block = 32 rows x 8 cols.
__global__ void final_kernel(const float* __restrict__ h,
                             const float* __restrict__ Wc,
                             const float* __restrict__ bc,
                             float* __restrict__ out) {
    __shared__ float Wcs[HD * NC];
    __shared__ float hs[32][HD + 1];
    int tid = threadIdx.x;
    for (int i = tid; i < HD * NC; i += 256) Wcs[i] = Wc[i];
    int base = blockIdx.x * 32;
    for (int i = tid; i < 32 * (HD / 4); i += 256) {
        int r = i >> 5, c = i & 31;
        int row = base + r;
        float4 v = make_float4(0.f, 0.f, 0.f, 0.f);
        if (row < NN) v = ((const float4*)(h + (size_t)row * HD))[c];
        hs[r][c * 4 + 0] = v.x; hs[r][c * 4 + 1] = v.y;
        hs[r][c * 4 + 2] = v.z; hs[r][c * 4 + 3] = v.w;
    }
    __syncthreads();
    int r = tid >> 3, c = tid & 7;
    float acc = bc[c];
    #pragma unroll 8
    for (int k = 0; k < HD; k++) acc += hs[r][k] * Wcs[k * NC + c];
    int row = base + r;
    if (row < NN) out[(size_t)row * NC + c] = acc;
}

// ---------------------------------------------------------------------------
extern "C" void kernel_launch(void* const* d_in, const int* in_sizes, int n_in,
                              void* d_out, int out_size) {
    const float* node_feat = (const float*)d_in[0];
    const int*   src       = (const int*)d_in[1];
    const int*   dst       = (const int*)d_in[2];
    const float* W1  = (const float*)d_in[3];
    const float* b1  = (const float*)d_in[4];
    const float* W2  = (const float*)d_in[5];
    const float* b2  = (const float*)d_in[6];
    const float* g1  = (const float*)d_in[7];
    const float* be1 = (const float*)d_in[8];
    const float* g2  = (const float*)d_in[9];
    const float* be2 = (const float*)d_in[10];
    const float* Wn1 = (const float*)d_in[11];
    const float* bn1 = (const float*)d_in[12];
    const float* Wn2 = (const float*)d_in[13];
    const float* bn2 = (const float*)d_in[14];
    const float* Wc  = (const float*)d_in[15];
    const float* bc  = (const float*)d_in[16];
    float* out = (float*)d_out;

    float *pA, *pB, *pOutN, *pInN, *pDegS, *pDegD, *pStats;
    cudaGetSymbolAddress((void**)&pA, g_A);
    cudaGetSymbolAddress((void**)&pB, g_B);
    cudaGetSymbolAddress((void**)&pOutN, g_outnorm);
    cudaGetSymbolAddress((void**)&pInN, g_innorm);
    cudaGetSymbolAddress((void**)&pDegS, g_degs);
    cudaGetSymbolAddress((void**)&pDegD, g_degd);
    cudaGetSymbolAddress((void**)&pStats, g_stats);

    const int smem_gemm = (HD * HD + 64 * HD) * (int)sizeof(float);  // 96 KB
    static bool attr_set = false;
    cudaFuncSetAttribute(gemm_kernel, cudaFuncAttributeMaxDynamicSharedMemorySize, smem_gemm);
    (void)attr_set;

    const int TB = 256;
    const int gridN = (NN + TB - 1) / TB;
    const int gridE = (EE + TB - 1) / TB;
    const int gridScatter = (int)(((long long)EE * 32 + TB - 1) / TB);
    const int gridAgg = (NN * (HD / 4) + TB - 1) / TB;
    const int gridGemm = (NN + 63) / 64;
    const int gridBN = (int)(((long long)NN * HD + TB - 1) / TB);
    const int gridFinal = (NN + 31) / 32;

    // degrees + norms
    zero_deg_kernel<<<gridN, TB>>>(pDegS, pDegD);
    deg_kernel<<<gridE, TB>>>(src, dst, pDegS, pDegD);
    norm_kernel<<<gridN, TB>>>(pDegS, pDegD, pOutN, pInN);

    // conv1: aggregate(node_feat) -> A ; B = A@W1+b1 ; BN1 + lrelu
    zero_agg_kernel<<<gridAgg, TB>>>((float4*)pA);
    scatter_kernel<<<gridScatter, TB>>>(node_feat, src, dst, pOutN, pA);
    gemm_kernel<<<gridGemm, TB, smem_gemm>>>(pA, pInN, W1, b1, pB, 0);
    zero_stats_kernel<<<1, 256>>>(pStats);
    stats_kernel<<<512, 256>>>(pB, pStats);
    bn_apply_kernel<<<gridBN, TB>>>(pB, g1, be1, pStats);

    // conv2
    zero_agg_kernel<<<gridAgg, TB>>>((float4*)pA);
    scatter_kernel<<<gridScatter, TB>>>(pB, src, dst, pOutN, pA);
    gemm_kernel<<<gridGemm, TB, smem_gemm>>>(pA, pInN, W2, b2, pB, 0);
    zero_stats_kernel<<<1, 256>>>(pStats);
    stats_kernel<<<512, 256>>>(pB, pStats);
    bn_apply_kernel<<<gridBN, TB>>>(pB, g2, be2, pStats);

    // convnode1: aggregate -> A ; B = lrelu(A@Wn1+bn1)
    zero_agg_kernel<<<gridAgg, TB>>>((float4*)pA);
    scatter_kernel<<<gridScatter, TB>>>(pB, src, dst, pOutN, pA);
    gemm_kernel<<<gridGemm, TB, smem_gemm>>>(pA, pInN, Wn1, bn1, pB, 1);

    // convnode2
    zero_agg_kernel<<<gridAgg, TB>>>((float4*)pA);
    scatter_kernel<<<gridScatter, TB>>>(pB, src, dst, pOutN, pA);
    gemm_kernel<<<gridGemm, TB, smem_gemm>>>(pA, pInN, Wn2, bn2, pB, 1);

    // classifier
    final_kernel<<<gridFinal, TB>>>(pB, Wc, bc, out);
}

// round 2
// speedup vs baseline: 1.5755x; 1.5755x over previous
#include <cuda_runtime.h>

#define NN 100000
#define EE 1600000
#define HD 128
#define NC 8
#define EPS_BN 1e-5f
#define SLOPE 0.01f

#define SCAN_BLK 1024
#define SCAN_GRID ((NN + SCAN_BLK - 1) / SCAN_BLK)   // 98

// ---- device scratch (allocation-free) ----
__device__ float g_A[(size_t)NN * HD];
__device__ float g_B[(size_t)NN * HD];
__device__ float g_outnorm[NN];
__device__ float g_innorm[NN];
__device__ int   g_srccnt[NN];
__device__ int   g_dstcnt[NN];
__device__ int   g_excl[NN];
__device__ int   g_blksum[SCAN_GRID];
__device__ int   g_rowptr[NN + 1];
__device__ int   g_cursor[NN];
__device__ int   g_esrc[EE];
__device__ float g_stats[2 * HD];

// ---------------------------------------------------------------------------
__global__ void zero_cnt_kernel(int* a, int* b) {
    int i = blockIdx.x * blockDim.x + threadIdx.x;
    if (i < NN) { a[i] = 0; b[i] = 0; }
}

__global__ void zero_stats_kernel(float* stats) {
    int i = threadIdx.x;
    if (i < 2 * HD) stats[i] = 0.f;
}

__global__ void hist_kernel(const int* __restrict__ src, const int* __restrict__ dst,
                            int* srccnt, int* dstcnt) {
    int e = blockIdx.x * blockDim.x + threadIdx.x;
    if (e >= EE) return;
    atomicAdd(&srccnt[src[e]], 1);
    atomicAdd(&dstcnt[dst[e]], 1);
}

__global__ void norm_kernel(const int* __restrict__ srccnt, const int* __restrict__ dstcnt,
                            float* outnorm, float* innorm) {
    int i = blockIdx.x * blockDim.x + threadIdx.x;
    if (i >= NN) return;
    outnorm[i] = rsqrtf(fmaxf((float)srccnt[i], 1.f));
    innorm[i]  = rsqrtf(fmaxf((float)dstcnt[i], 1.f));
}

// Blockwise exclusive scan of dst counts
__global__ void scan1_kernel(const int* __restrict__ cnt, int* excl, int* blksum) {
    __shared__ int sh[SCAN_BLK];
    int i = blockIdx.x * SCAN_BLK + threadIdx.x;
    int v = (i < NN) ? cnt[i] : 0;
    sh[threadIdx.x] = v;
    __syncthreads();
    for (int off = 1; off < SCAN_BLK; off <<= 1) {
        int t = (threadIdx.x >= off) ? sh[threadIdx.x - off] : 0;
        __syncthreads();
        sh[threadIdx.x] += t;
        __syncthreads();
    }
    if (i < NN) excl[i] = sh[threadIdx.x] - v;
    if (threadIdx.x == SCAN_BLK - 1) blksum[blockIdx.x] = sh[threadIdx.x];
}

__global__ void scan2_kernel(int* blksum) {
    __shared__ int sh[1024];
    int i = threadIdx.x;
    int v = (i < SCAN_GRID) ? blksum[i] : 0;
    sh[i] = v;
    __syncthreads();
    for (int off = 1; off < 1024; off <<= 1) {
        int t = (i >= off) ? sh[i - off] : 0;
        __syncthreads();
        sh[i] += t;
        __syncthreads();
    }
    if (i < SCAN_GRID) blksum[i] = sh[i] - v;   // exclusive
}

__global__ void scan3_kernel(const int* __restrict__ excl, const int* __restrict__ blksum,
                             int* rowptr, int* cursor) {
    int i = blockIdx.x * SCAN_BLK + threadIdx.x;
    if (i < NN) {
        int r = excl[i] + blksum[blockIdx.x];
        rowptr[i] = r;
        cursor[i] = r;
    }
    if (i == 0) rowptr[NN] = EE;
}

__global__ void fill_kernel(const int* __restrict__ src, const int* __restrict__ dst,
                            int* cursor, int* esrc) {
    int e = blockIdx.x * blockDim.x + threadIdx.x;
    if (e >= EE) return;
    int p = atomicAdd(&cursor[dst[e]], 1);
    esrc[p] = src[e];
}

// ---------------------------------------------------------------------------
// One warp per dst node: gather neighbor rows (x[s]*outnorm[s]), sum in regs,
// scale by innorm[dst], write once. No float atomics, no pre-zeroing.
__global__ void agg_kernel(const float* __restrict__ x,
                           const int* __restrict__ rowptr,
                           const int* __restrict__ esrc,
                           const float* __restrict__ outnorm,
                           const float* __restrict__ innorm,
                           float* __restrict__ agg) {
    int warp = (blockIdx.x * blockDim.x + threadIdx.x) >> 5;
    if (warp >= NN) return;
    int lane = threadIdx.x & 31;
    int beg = rowptr[warp], end = rowptr[warp + 1];
    const float4* x4 = (const float4*)x;
    float4 acc = make_float4(0.f, 0.f, 0.f, 0.f);
    int j = beg;
    for (; j + 1 < end; j += 2) {
        int s0 = esrc[j], s1 = esrc[j + 1];
        float w0 = outnorm[s0], w1 = outnorm[s1];
        float4 v0 = x4[(size_t)s0 * 32 + lane];
        float4 v1 = x4[(size_t)s1 * 32 + lane];
        acc.x += w0 * v0.x + w1 * v1.x;
        acc.y += w0 * v0.y + w1 * v1.y;
        acc.z += w0 * v0.z + w1 * v1.z;
        acc.w += w0 * v0.w + w1 * v1.w;
    }
    if (j < end) {
        int s = esrc[j];
        float w = outnorm[s];
        float4 v = x4[(size_t)s * 32 + lane];
        acc.x += w * v.x; acc.y += w * v.y; acc.z += w * v.z; acc.w += w * v.w;
    }
    float in = innorm[warp];
    acc.x *= in; acc.y *= in; acc.z *= in; acc.w *= in;
    ((float4*)agg)[(size_t)warp * 32 + lane] = acc;
}

// ---------------------------------------------------------------------------
// out[row] = A[row] @ W + b; optional LeakyReLU; optional fused BN col-stats.
__global__ void gemm_kernel(const float* __restrict__ A,
                            const float* __restrict__ W,
                            const float* __restrict__ b,
                            float* __restrict__ out, int act,
                            float* __restrict__ stats) {
    extern __shared__ float sm[];
    float* Ws = sm;               // 128*128
    float* As = sm + HD * HD;     // 64*128
    int tid = threadIdx.x;
    int block_row = blockIdx.x * 64;

    {
        float4* Wsv = (float4*)Ws;
        const float4* Wv = (const float4*)W;
        #pragma unroll
        for (int i = tid; i < HD * (HD / 4); i += 256) Wsv[i] = Wv[i];
    }
    for (int i = tid; i < 64 * (HD / 4); i += 256) {
        int r = i >> 5, c4 = i & 31;
        int row = block_row + r;
        float4 v = make_float4(0.f, 0.f, 0.f, 0.f);
        if (row < NN) v = ((const float4*)(A + (size_t)row * HD))[c4];
        ((float4*)(As + r * HD))[c4] = v;
    }
    __syncthreads();

    int tx = tid & 31;
    int ty = tid >> 5;
    float acc[8][4];
    float4 bb = ((const float4*)b)[tx];
    #pragma unroll
    for (int r = 0; r < 8; r++) { acc[r][0] = bb.x; acc[r][1] = bb.y; acc[r][2] = bb.z; acc[r][3] = bb.w; }

    const float* Arow = As + ty * 8 * HD;
    #pragma unroll 4
    for (int k = 0; k < HD; k++) {
        float4 w = ((const float4*)(Ws + k * HD))[tx];
        #pragma unroll
        for (int r = 0; r < 8; r++) {
            float a = Arow[r * HD + k];
            acc[r][0] += a * w.x; acc[r][1] += a * w.y;
            acc[r][2] += a * w.z; acc[r][3] += a * w.w;
        }
    }

    float s1v[4] = {0.f, 0.f, 0.f, 0.f};
    float s2v[4] = {0.f, 0.f, 0.f, 0.f};
    #pragma unroll
    for (int r = 0; r < 8; r++) {
        int row = block_row + ty * 8 + r;
        if (row >= NN) continue;
        float4 o = make_float4(acc[r][0], acc[r][1], acc[r][2], acc[r][3]);
        if (act) {
            o.x = o.x >= 0.f ? o.x : SLOPE * o.x;
            o.y = o.y >= 0.f ? o.y : SLOPE * o.y;
            o.z = o.z >= 0.f ? o.z : SLOPE * o.z;
            o.w = o.w >= 0.f ? o.w : SLOPE * o.w;
        }
        ((float4*)(out + (size_t)row * HD))[tx] = o;
        s1v[0] += o.x; s1v[1] += o.y; s1v[2] += o.z; s1v[3] += o.w;
        s2v[0] += o.x * o.x; s2v[1] += o.y * o.y; s2v[2] += o.z * o.z; s2v[3] += o.w * o.w;
    }

    if (stats) {
        __syncthreads();
        float* red = sm;   // reuse: 256 threads * 8 floats
        #pragma unroll
        for (int k = 0; k < 4; k++) { red[tid * 8 + k] = s1v[k]; red[tid * 8 + 4 + k] = s2v[k]; }
        __syncthreads();
        if (ty == 0) {
            #pragma unroll
            for (int k = 0; k < 4; k++) {
                float a1 = 0.f, a2 = 0.f;
                #pragma unroll
                for (int g = 0; g < 8; g++) {
                    a1 += red[(g * 32 + tx) * 8 + k];
                    a2 += red[(g * 32 + tx) * 8 + 4 + k];
                }
                atomicAdd(&stats[tx * 4 + k], a1);
                atomicAdd(&stats[HD + tx * 4 + k], a2);
            }
        }
    }
}

// BN (training-mode, biased var) + LeakyReLU, in place.
__global__ void bn_apply_kernel(float* __restrict__ x,
                                const float* __restrict__ gamma,
                                const float* __restrict__ beta,
                                const float* __restrict__ stats) {
    long long i = (long long)blockIdx.x * blockDim.x + threadIdx.x;
    const long long total = (long long)NN * HD;
    if (i >= total) return;
    int col = (int)(i & (HD - 1));
    float mean = stats[col] * (1.f / NN);
    float var = stats[HD + col] * (1.f / NN) - mean * mean;
    float rstd = rsqrtf(var + EPS_BN);
    float v = (x[i] - mean) * rstd * gamma[col] + beta[col];
    x[i] = v >= 0.f ? v : SLOPE * v;
}

// Final classifier: out[N,8] = h @ Wc + bc.
__global__ void final_kernel(const float* __restrict__ h,
                             const float* __restrict__ Wc,
                             const float* __restrict__ bc,
                             float* __restrict__ out) {
    __shared__ float Wcs[HD * NC];
    __shared__ float hs[32][HD + 1];
    int tid = threadIdx.x;
    for (int i = tid; i < HD * NC; i += 256) Wcs[i] = Wc[i];
    int base = blockIdx.x * 32;
    for (int i = tid; i < 32 * (HD / 4); i += 256) {
        int r = i >> 5, c = i & 31;
        int row = base + r;
        float4 v = make_float4(0.f, 0.f, 0.f, 0.f);
        if (row < NN) v = ((const float4*)(h + (size_t)row * HD))[c];
        hs[r][c * 4 + 0] = v.x; hs[r][c * 4 + 1] = v.y;
        hs[r][c * 4 + 2] = v.z; hs[r][c * 4 + 3] = v.w;
    }
    __syncthreads();
    int r = tid >> 3, c = tid & 7;
    float acc = bc[c];
    #pragma unroll 8
    for (int k = 0; k < HD; k++) acc += hs[r][k] * Wcs[k * NC + c];
    int row = base + r;
    if (row < NN) out[(size_t)row * NC + c] = acc;
}

// ---------------------------------------------------------------------------
extern "C" void kernel_launch(void* const* d_in, const int* in_sizes, int n_in,
                              void* d_out, int out_size) {
    const float* node_feat = (const float*)d_in[0];
    const int*   src       = (const int*)d_in[1];
    const int*   dst       = (const int*)d_in[2];
    const float* W1  = (const float*)d_in[3];
    const float* b1  = (const float*)d_in[4];
    const float* W2  = (const float*)d_in[5];
    const float* b2  = (const float*)d_in[6];
    const float* g1  = (const float*)d_in[7];
    const float* be1 = (const float*)d_in[8];
    const float* g2  = (const float*)d_in[9];
    const float* be2 = (const float*)d_in[10];
    const float* Wn1 = (const float*)d_in[11];
    const float* bn1 = (const float*)d_in[12];
    const float* Wn2 = (const float*)d_in[13];
    const float* bn2 = (const float*)d_in[14];
    const float* Wc  = (const float*)d_in[15];
    const float* bc  = (const float*)d_in[16];
    float* out = (float*)d_out;

    float *pA, *pB, *pOutN, *pInN, *pStats;
    int *pSrcC, *pDstC, *pExcl, *pBlk, *pRow, *pCur, *pEsrc;
    cudaGetSymbolAddress((void**)&pA, g_A);
    cudaGetSymbolAddress((void**)&pB, g_B);
    cudaGetSymbolAddress((void**)&pOutN, g_outnorm);
    cudaGetSymbolAddress((void**)&pInN, g_innorm);
    cudaGetSymbolAddress((void**)&pStats, g_stats);
    cudaGetSymbolAddress((void**)&pSrcC, g_srccnt);
    cudaGetSymbolAddress((void**)&pDstC, g_dstcnt);
    cudaGetSymbolAddress((void**)&pExcl, g_excl);
    cudaGetSymbolAddress((void**)&pBlk, g_blksum);
    cudaGetSymbolAddress((void**)&pRow, g_rowptr);
    cudaGetSymbolAddress((void**)&pCur, g_cursor);
    cudaGetSymbolAddress((void**)&pEsrc, g_esrc);

    const int smem_gemm = (HD * HD + 64 * HD) * (int)sizeof(float);  // 96 KB
    cudaFuncSetAttribute(gemm_kernel, cudaFuncAttributeMaxDynamicSharedMemorySize, smem_gemm);

    const int TB = 256;
    const int gridN = (NN + TB - 1) / TB;
    const int gridE = (EE + TB - 1) / TB;
    const int gridAggW = (NN * 32 + TB - 1) / TB;   // one warp per node
    const int gridGemm = (NN + 63) / 64;
    const int gridBN = (int)(((long long)NN * HD + TB - 1) / TB);
    const int gridFinal = (NN + 31) / 32;

    // ---- CSR build + norms ----
    zero_cnt_kernel<<<gridN, TB>>>(pSrcC, pDstC);
    hist_kernel<<<gridE, TB>>>(src, dst, pSrcC, pDstC);
    norm_kernel<<<gridN, TB>>>(pSrcC, pDstC, pOutN, pInN);
    scan1_kernel<<<SCAN_GRID, SCAN_BLK>>>(pDstC, pExcl, pBlk);
    scan2_kernel<<<1, 1024>>>(pBlk);
    scan3_kernel<<<SCAN_GRID, SCAN_BLK>>>(pExcl, pBlk, pRow, pCur);
    fill_kernel<<<gridE, TB>>>(src, dst, pCur, pEsrc);

    // ---- conv1 ----
    agg_kernel<<<gridAggW, TB>>>(node_feat, pRow, pEsrc, pOutN, pInN, pA);
    zero_stats_kernel<<<1, 256>>>(pStats);
    gemm_kernel<<<gridGemm, TB, smem_gemm>>>(pA, W1, b1, pB, 0, pStats);
    bn_apply_kernel<<<gridBN, TB>>>(pB, g1, be1, pStats);

    // ---- conv2 ----
    agg_kernel<<<gridAggW, TB>>>(pB, pRow, pEsrc, pOutN, pInN, pA);
    zero_stats_kernel<<<1, 256>>>(pStats);
    gemm_kernel<<<gridGemm, TB, smem_gemm>>>(pA, W2, b2, pB, 0, pStats);
    bn_apply_kernel<<<gridBN, TB>>>(pB, g2, be2, pStats);

    // ---- convnode1 ----
    agg_kernel<<<gridAggW, TB>>>(pB, pRow, pEsrc, pOutN, pInN, pA);
    gemm_kernel<<<gridGemm, TB, smem_gemm>>>(pA, Wn1, bn1, pB, 1, nullptr);

    // ---- convnode2 ----
    agg_kernel<<<gridAggW, TB>>>(pB, pRow, pEsrc, pOutN, pInN, pA);
    gemm_kernel<<<gridGemm, TB, smem_gemm>>>(pA, Wn2, bn2, pB, 1, nullptr);

    // ---- classifier ----
    final_kernel<<<gridFinal, TB>>>(pB, Wc, bc, out);
}

// round 4
// speedup vs baseline: 1.9096x; 1.2121x over previous
#include <cuda_runtime.h>
#include <cuda_bf16.h>
#include <cstdint>

#define NN 100000
#define EE 1600000
#define HD 128
#define NC 8
#define EPS_BN 1e-5f
#define SLOPE 0.01f

#define SCAN_BLK 1024
#define SCAN_GRID ((NN + SCAN_BLK - 1) / SCAN_BLK)   // 98
#define GEMM_GRID ((NN + 127) / 128)                 // 782

// padded smem row stride (bf16 elems): 128 + 8 -> conflict-free ldmatrix
#define LDA 136
#define OFF_A_HI 0
#define OFF_A_LO (128 * LDA * 2)            // 34816
#define OFF_W_HI (2 * 128 * LDA * 2)        // 69632
#define OFF_W_LO (3 * 128 * LDA * 2)        // 104448
#define OFF_STATS (4 * 128 * LDA * 2)       // 139264
#define SM_TOTAL (OFF_STATS + 256 * 4)      // 140288

// ---- device scratch (allocation-free) ----
__device__ float g_A[(size_t)NN * HD];
__device__ float g_B[(size_t)NN * HD];
__device__ float g_outnorm[NN];
__device__ float g_innorm[NN];
__device__ int   g_srccnt[NN];
__device__ int   g_dstcnt[NN];
__device__ int   g_excl[NN];
__device__ int   g_blksum[SCAN_GRID];
__device__ int   g_rowptr[NN + 1];
__device__ int   g_cursor[NN];
__device__ int   g_esrc[EE];
__device__ float g_stats[2 * HD];
__device__ float g_scale[HD];
__device__ float g_bias[HD];
// 4 weights x {hi,lo} x W^T[n][k] bf16
__device__ __nv_bfloat16 g_Wtb[8 * 16384];

// ============================ CSR build =====================================
__global__ void zero_cnt_kernel(int* a, int* b) {
    int i = blockIdx.x * blockDim.x + threadIdx.x;
    if (i < NN) { a[i] = 0; b[i] = 0; }
}
__global__ void zero_stats_kernel(float* stats) {
    int i = threadIdx.x;
    if (i < 2 * HD) stats[i] = 0.f;
}
__global__ void hist_kernel(const int* __restrict__ src, const int* __restrict__ dst,
                            int* srccnt, int* dstcnt) {
    int e = blockIdx.x * blockDim.x + threadIdx.x;
    if (e >= EE) return;
    atomicAdd(&srccnt[src[e]], 1);
    atomicAdd(&dstcnt[dst[e]], 1);
}
__global__ void norm_kernel(const int* __restrict__ srccnt, const int* __restrict__ dstcnt,
                            float* outnorm, float* innorm) {
    int i = blockIdx.x * blockDim.x + threadIdx.x;
    if (i >= NN) return;
    outnorm[i] = rsqrtf(fmaxf((float)srccnt[i], 1.f));
    innorm[i]  = rsqrtf(fmaxf((float)dstcnt[i], 1.f));
}
__global__ void scan1_kernel(const int* __restrict__ cnt, int* excl, int* blksum) {
    __shared__ int sh[SCAN_BLK];
    int i = blockIdx.x * SCAN_BLK + threadIdx.x;
    int v = (i < NN) ? cnt[i] : 0;
    sh[threadIdx.x] = v;
    __syncthreads();
    for (int off = 1; off < SCAN_BLK; off <<= 1) {
        int t = (threadIdx.x >= off) ? sh[threadIdx.x - off] : 0;
        __syncthreads();
        sh[threadIdx.x] += t;
        __syncthreads();
    }
    if (i < NN) excl[i] = sh[threadIdx.x] - v;
    if (threadIdx.x == SCAN_BLK - 1) blksum[blockIdx.x] = sh[threadIdx.x];
}
__global__ void scan2_kernel(int* blksum) {
    __shared__ int sh[1024];
    int i = threadIdx.x;
    int v = (i < SCAN_GRID) ? blksum[i] : 0;
    sh[i] = v;
    __syncthreads();
    for (int off = 1; off < 1024; off <<= 1) {
        int t = (i >= off) ? sh[i - off] : 0;
        __syncthreads();
        sh[i] += t;
        __syncthreads();
    }
    if (i < SCAN_GRID) blksum[i] = sh[i] - v;
}
__global__ void scan3_kernel(const int* __restrict__ excl, const int* __restrict__ blksum,
                             int* rowptr, int* cursor) {
    int i = blockIdx.x * SCAN_BLK + threadIdx.x;
    if (i < NN) {
        int r = excl[i] + blksum[blockIdx.x];
        rowptr[i] = r;
        cursor[i] = r;
    }
    if (i == 0) rowptr[NN] = EE;
}
__global__ void fill_kernel(const int* __restrict__ src, const int* __restrict__ dst,
                            int* cursor, int* esrc) {
    int e = blockIdx.x * blockDim.x + threadIdx.x;
    if (e >= EE) return;
    int p = atomicAdd(&cursor[dst[e]], 1);
    esrc[p] = src[e];
}

// ============================ aggregation ===================================
// One warp per dst node; optional fused BN affine + LeakyReLU on gathered rows.
__global__ void agg_kernel(const float* __restrict__ x,
                           const int* __restrict__ rowptr,
                           const int* __restrict__ esrc,
                           const float* __restrict__ outnorm,
                           const float* __restrict__ innorm,
                           float* __restrict__ agg,
                           const float* __restrict__ scale,
                           const float* __restrict__ bias) {
    int warp = (blockIdx.x * blockDim.x + threadIdx.x) >> 5;
    if (warp >= NN) return;
    int lane = threadIdx.x & 31;
    int beg = rowptr[warp], end = rowptr[warp + 1];
    const float4* x4 = (const float4*)x;
    float4 acc = make_float4(0.f, 0.f, 0.f, 0.f);

    if (scale) {
        float4 sc = ((const float4*)scale)[lane];
        float4 bi = ((const float4*)bias)[lane];
        for (int j = beg; j < end; j++) {
            int s = esrc[j];
            float w = outnorm[s];
            float4 v = x4[(size_t)s * 32 + lane];
            float tx = fmaf(v.x, sc.x, bi.x); tx = tx >= 0.f ? tx : SLOPE * tx;
            float ty = fmaf(v.y, sc.y, bi.y); ty = ty >= 0.f ? ty : SLOPE * ty;
            float tz = fmaf(v.z, sc.z, bi.z); tz = tz >= 0.f ? tz : SLOPE * tz;
            float tw = fmaf(v.w, sc.w, bi.w); tw = tw >= 0.f ? tw : SLOPE * tw;
            acc.x += w * tx; acc.y += w * ty; acc.z += w * tz; acc.w += w * tw;
        }
    } else {
        int j = beg;
        for (; j + 1 < end; j += 2) {
            int s0 = esrc[j], s1 = esrc[j + 1];
            float w0 = outnorm[s0], w1 = outnorm[s1];
            float4 v0 = x4[(size_t)s0 * 32 + lane];
            float4 v1 = x4[(size_t)s1 * 32 + lane];
            acc.x += w0 * v0.x + w1 * v1.x;
            acc.y += w0 * v0.y + w1 * v1.y;
            acc.z += w0 * v0.z + w1 * v1.z;
            acc.w += w0 * v0.w + w1 * v1.w;
        }
        if (j < end) {
            int s = esrc[j];
            float w = outnorm[s];
            float4 v = x4[(size_t)s * 32 + lane];
            acc.x += w * v.x; acc.y += w * v.y; acc.z += w * v.z; acc.w += w * v.w;
        }
    }
    float in = innorm[warp];
    acc.x *= in; acc.y *= in; acc.z *= in; acc.w *= in;
    ((float4*)agg)[(size_t)warp * 32 + lane] = acc;
}

// ===================== weight prep: W^T hi/lo bf16 ==========================
__global__ void prep_w_kernel(const float* __restrict__ Wa, const float* __restrict__ Wb,
                              const float* __restrict__ Wc_, const float* __restrict__ Wd,
                              __nv_bfloat16* __restrict__ Wt) {
    const float* W = (blockIdx.x == 0) ? Wa : (blockIdx.x == 1) ? Wb : (blockIdx.x == 2) ? Wc_ : Wd;
    __nv_bfloat16* hi_t = Wt + (size_t)blockIdx.x * 2 * 16384;
    __nv_bfloat16* lo_t = hi_t + 16384;
    for (int idx = threadIdx.x; idx < HD * HD; idx += 256) {
        int k = idx >> 7, n = idx & 127;
        float w = W[idx];
        __nv_bfloat16 h = __float2bfloat16_rn(w);
        float r = w - __bfloat162float(h);
        hi_t[n * HD + k] = h;
        lo_t[n * HD + k] = __float2bfloat16_rn(r);
    }
}

// ================= mma.sync bf16 3-pass GEMM (128x128 tile) =================
__device__ __forceinline__ uint32_t smem_u32(const void* p) {
    uint32_t a;
    asm("{ .reg .u64 t; cvta.to.shared.u64 t, %1; cvt.u32.u64 %0, t; }" : "=r"(a) : "l"(p));
    return a;
}
#define LDSM_X4(r0, r1, r2, r3, a) \
    asm volatile("ldmatrix.sync.aligned.m8n8.x4.shared.b16 {%0,%1,%2,%3}, [%4];" \
        : "=r"(r0), "=r"(r1), "=r"(r2), "=r"(r3) : "r"(a))
#define LDSM_X2(r0, r1, a) \
    asm volatile("ldmatrix.sync.aligned.m8n8.x2.shared.b16 {%0,%1}, [%2];" \
        : "=r"(r0), "=r"(r1) : "r"(a))
#define MMA16816(c, A0, A1, A2, A3, B0, B1) \
    asm volatile("mma.sync.aligned.m16n8k16.row.col.f32.bf16.bf16.f32 " \
        "{%0,%1,%2,%3}, {%4,%5,%6,%7}, {%8,%9}, {%0,%1,%2,%3};" \
        : "+f"((c)[0]), "+f"((c)[1]), "+f"((c)[2]), "+f"((c)[3]) \
        : "r"(A0), "r"(A1), "r"(A2), "r"(A3), "r"(B0), "r"(B1))

__global__ void __launch_bounds__(256, 1)
gemm_mma_kernel(const float* __restrict__ A,
                const __nv_bfloat16* __restrict__ Wt_hi,
                const __nv_bfloat16* __restrict__ Wt_lo,
                const float* __restrict__ bvec,
                float* __restrict__ out, int act,
                float* __restrict__ stats) {
    extern __shared__ char smem[];
    uint32_t sbase = smem_u32(smem);
    float* s_stats = (float*)(smem + OFF_STATS);
    int tid = threadIdx.x;
    int wid = tid >> 5;
    int lane = tid & 31;
    int block_row = blockIdx.x * 128;

    if (stats && tid < 256) s_stats[tid] = 0.f;

    // ---- load A tile -> bf16 hi/lo in smem (padded) ----
    {
        int r = tid >> 1;                    // 0..127
        int halfc = (tid & 1) * 64;          // col base
        int grow = block_row + r;
        char* dh = smem + OFF_A_HI + (r * LDA + halfc) * 2;
        char* dl = smem + OFF_A_LO + (r * LDA + halfc) * 2;
        if (grow < NN) {
            const float4* ap = (const float4*)(A + (size_t)grow * HD + halfc);
            #pragma unroll
            for (int q = 0; q < 16; q++) {
                float4 v = ap[q];
                __nv_bfloat16 h0 = __float2bfloat16_rn(v.x);
                __nv_bfloat16 h1 = __float2bfloat16_rn(v.y);
                __nv_bfloat16 h2 = __float2bfloat16_rn(v.z);
                __nv_bfloat16 h3 = __float2bfloat16_rn(v.w);
                __nv_bfloat162 ph0 = {h0, h1}, ph1 = {h2, h3};
                __nv_bfloat162 pl0 = {__float2bfloat16_rn(v.x - __bfloat162float(h0)),
                                      __float2bfloat16_rn(v.y - __bfloat162float(h1))};
                __nv_bfloat162 pl1 = {__float2bfloat16_rn(v.z - __bfloat162float(h2)),
                                      __float2bfloat16_rn(v.w - __bfloat162float(h3))};
                ((__nv_bfloat162*)(dh + q * 8))[0] = ph0;
                ((__nv_bfloat162*)(dh + q * 8))[1] = ph1;
                ((__nv_bfloat162*)(dl + q * 8))[0] = pl0;
                ((__nv_bfloat162*)(dl + q * 8))[1] = pl1;
            }
        } else {
            #pragma unroll
            for (int q = 0; q < 16; q++) {
                ((uint2*)(dh + q * 8))[0] = make_uint2(0u, 0u);
                ((uint2*)(dl + q * 8))[0] = make_uint2(0u, 0u);
            }
        }
    }
    // ---- copy W^T hi/lo into padded smem ----
    {
        const uint32_t* wh = (const uint32_t*)Wt_hi;
        const uint32_t* wl = (const uint32_t*)Wt_lo;
        #pragma unroll
        for (int i = tid; i < 8192; i += 256) {
            int n = i >> 6, kp = i & 63;
            *(uint32_t*)(smem + OFF_W_HI + n * (LDA * 2) + kp * 4) = wh[i];
            *(uint32_t*)(smem + OFF_W_LO + n * (LDA * 2) + kp * 4) = wl[i];
        }
    }
    __syncthreads();

    // ---- mma mainloop ----
    int warp_m = wid >> 1;          // 0..3 -> rows 32*warp_m
    int warp_n = wid & 1;           // 0..1 -> cols 64*warp_n
    int sub = lane >> 3, r8 = lane & 7;
    int arow = warp_m * 32 + (sub & 1) * 8 + r8;
    int akoff = (sub >> 1) * 8;
    uint32_t aAh0 = sbase + OFF_A_HI + (arow * LDA + akoff) * 2;
    uint32_t aAh1 = aAh0 + 16 * LDA * 2;
    uint32_t aAl0 = aAh0 + (OFF_A_LO - OFF_A_HI);
    uint32_t aAl1 = aAh1 + (OFF_A_LO - OFF_A_HI);
    int bl = lane & 15;
    int brow = warp_n * 64 + (bl & 7);
    int bkoff = (bl >> 3) * 8;
    uint32_t aBh = sbase + OFF_W_HI + (brow * LDA + bkoff) * 2;
    uint32_t aBl = aBh + (OFF_W_LO - OFF_W_HI);

    float acc[2][8][4];
    #pragma unroll
    for (int m = 0; m < 2; m++)
        #pragma unroll
        for (int n = 0; n < 8; n++)
            #pragma unroll
            for (int q = 0; q < 4; q++) acc[m][n][q] = 0.f;

    #pragma unroll
    for (int ks = 0; ks < 8; ks++) {
        uint32_t ah[2][4], al[2][4];
        LDSM_X4(ah[0][0], ah[0][1], ah[0][2], ah[0][3], aAh0 + ks * 32);
        LDSM_X4(ah[1][0], ah[1][1], ah[1][2], ah[1][3], aAh1 + ks * 32);
        LDSM_X4(al[0][0], al[0][1], al[0][2], al[0][3], aAl0 + ks * 32);
        LDSM_X4(al[1][0], al[1][1], al[1][2], al[1][3], aAl1 + ks * 32);
        #pragma unroll
        for (int n = 0; n < 8; n++) {
            uint32_t bh0, bh1, bl0, bl1;
            LDSM_X2(bh0, bh1, aBh + n * (8 * LDA * 2) + ks * 32);
            LDSM_X2(bl0, bl1, aBl + n * (8 * LDA * 2) + ks * 32);
            #pragma unroll
            for (int m = 0; m < 2; m++) {
                MMA16816(acc[m][n], ah[m][0], ah[m][1], ah[m][2], ah[m][3], bh0, bh1);
                MMA16816(acc[m][n], ah[m][0], ah[m][1], ah[m][2], ah[m][3], bl0, bl1);
                MMA16816(acc[m][n], al[m][0], al[m][1], al[m][2], al[m][3], bh0, bh1);
            }
        }
    }

    // ---- epilogue ----
    int gid = lane >> 2, tig = lane & 3;
    #pragma unroll
    for (int n = 0; n < 8; n++) {
        int col = warp_n * 64 + n * 8 + tig * 2;
        float b0 = __ldg(&bvec[col]), b1 = __ldg(&bvec[col + 1]);
        float s1c0 = 0.f, s1c1 = 0.f, s2c0 = 0.f, s2c1 = 0.f;
        #pragma unroll
        for (int m = 0; m < 2; m++) {
            int r0 = block_row + warp_m * 32 + m * 16 + gid;
            int r1 = r0 + 8;
            float f0 = acc[m][n][0] + b0;
            float f1 = acc[m][n][1] + b1;
            float f2 = acc[m][n][2] + b0;
            float f3 = acc[m][n][3] + b1;
            if (act) {
                f0 = f0 >= 0.f ? f0 : SLOPE * f0;
                f1 = f1 >= 0.f ? f1 : SLOPE * f1;
                f2 = f2 >= 0.f ? f2 : SLOPE * f2;
                f3 = f3 >= 0.f ? f3 : SLOPE * f3;
            }
            if (r0 < NN) {
                *(float2*)(out + (size_t)r0 * HD + col) = make_float2(f0, f1);
                s1c0 += f0; s1c1 += f1; s2c0 += f0 * f0; s2c1 += f1 * f1;
            }
            if (r1 < NN) {
                *(float2*)(out + (size_t)r1 * HD + col) = make_float2(f2, f3);
                s1c0 += f2; s1c1 += f3; s2c0 += f2 * f2; s2c1 += f3 * f3;
            }
        }
        if (stats) {
            #pragma unroll
            for (int o = 4; o <= 16; o <<= 1) {
                s1c0 += __shfl_xor_sync(0xFFFFFFFFu, s1c0, o);
                s1c1 += __shfl_xor_sync(0xFFFFFFFFu, s1c1, o);
                s2c0 += __shfl_xor_sync(0xFFFFFFFFu, s2c0, o);
                s2c1 += __shfl_xor_sync(0xFFFFFFFFu, s2c1, o);
            }
            if (gid == 0) {
                atomicAdd(&s_stats[col], s1c0);
                atomicAdd(&s_stats[col + 1], s1c1);
                atomicAdd(&s_stats[128 + col], s2c0);
                atomicAdd(&s_stats[128 + col + 1], s2c1);
            }
        }
    }
    if (stats) {
        __syncthreads();
        if (tid < 256) atomicAdd(&stats[tid], s_stats[tid]);
    }
}

// scale/bias from BN stats
__global__ void sb_kernel(const float* __restrict__ stats,
                          const float* __restrict__ gamma,
                          const float* __restrict__ beta,
                          float* __restrict__ scale, float* __restrict__ bias) {
    int c = threadIdx.x;
    float mean = stats[c] * (1.f / NN);
    float var = stats[HD + c] * (1.f / NN) - mean * mean;
    float r = rsqrtf(var + EPS_BN) * gamma[c];
    scale[c] = r;
    bias[c] = beta[c] - mean * r;
}

// Final classifier
__global__ void final_kernel(const float* __restrict__ h,
                             const float* __restrict__ Wc,
                             const float* __restrict__ bc,
                             float* __restrict__ out) {
    __shared__ float Wcs[HD * NC];
    __shared__ float hs[32][HD + 1];
    int tid = threadIdx.x;
    for (int i = tid; i < HD * NC; i += 256) Wcs[i] = Wc[i];
    int base = blockIdx.x * 32;
    for (int i = tid; i < 32 * (HD / 4); i += 256) {
        int r = i >> 5, c = i & 31;
        int row = base + r;
        float4 v = make_float4(0.f, 0.f, 0.f, 0.f);
        if (row < NN) v = ((const float4*)(h + (size_t)row * HD))[c];
        hs[r][c * 4 + 0] = v.x; hs[r][c * 4 + 1] = v.y;
        hs[r][c * 4 + 2] = v.z; hs[r][c * 4 + 3] = v.w;
    }
    __syncthreads();
    int r = tid >> 3, c = tid & 7;
    float acc = bc[c];
    #pragma unroll 8
    for (int k = 0; k < HD; k++) acc += hs[r][k] * Wcs[k * NC + c];
    int row = base + r;
    if (row < NN) out[(size_t)row * NC + c] = acc;
}

// ---------------------------------------------------------------------------
extern "C" void kernel_launch(void* const* d_in, const int* in_sizes, int n_in,
                              void* d_out, int out_size) {
    const float* node_feat = (const float*)d_in[0];
    const int*   src       = (const int*)d_in[1];
    const int*   dst       = (const int*)d_in[2];
    const float* W1  = (const float*)d_in[3];
    const float* b1  = (const float*)d_in[4];
    const float* W2  = (const float*)d_in[5];
    const float* b2  = (const float*)d_in[6];
    const float* g1  = (const float*)d_in[7];
    const float* be1 = (const float*)d_in[8];
    const float* g2  = (const float*)d_in[9];
    const float* be2 = (const float*)d_in[10];
    const float* Wn1 = (const float*)d_in[11];
    const float* bn1 = (const float*)d_in[12];
    const float* Wn2 = (const float*)d_in[13];
    const float* bn2 = (const float*)d_in[14];
    const float* Wc  = (const float*)d_in[15];
    const float* bc  = (const float*)d_in[16];
    float* out = (float*)d_out;

    float *pA, *pB, *pOutN, *pInN, *pStats, *pScale, *pBias;
    __nv_bfloat16* pWt;
    int *pSrcC, *pDstC, *pExcl, *pBlk, *pRow, *pCur, *pEsrc;
    cudaGetSymbolAddress((void**)&pA, g_A);
    cudaGetSymbolAddress((void**)&pB, g_B);
    cudaGetSymbolAddress((void**)&pOutN, g_outnorm);
    cudaGetSymbolAddress((void**)&pInN, g_innorm);
    cudaGetSymbolAddress((void**)&pStats, g_stats);
    cudaGetSymbolAddress((void**)&pWt, g_Wtb);
    cudaGetSymbolAddress((void**)&pScale, g_scale);
    cudaGetSymbolAddress((void**)&pBias, g_bias);
    cudaGetSymbolAddress((void**)&pSrcC, g_srccnt);
    cudaGetSymbolAddress((void**)&pDstC, g_dstcnt);
    cudaGetSymbolAddress((void**)&pExcl, g_excl);
    cudaGetSymbolAddress((void**)&pBlk, g_blksum);
    cudaGetSymbolAddress((void**)&pRow, g_rowptr);
    cudaGetSymbolAddress((void**)&pCur, g_cursor);
    cudaGetSymbolAddress((void**)&pEsrc, g_esrc);

    cudaFuncSetAttribute(gemm_mma_kernel, cudaFuncAttributeMaxDynamicSharedMemorySize, SM_TOTAL);

    const int TB = 256;
    const int gridN = (NN + TB - 1) / TB;
    const int gridE = (EE + TB - 1) / TB;
    const int gridAggW = (NN * 32 + TB - 1) / TB;
    const int gridFinal = (NN + 31) / 32;

    // ---- CSR build + norms + weight prep ----
    zero_cnt_kernel<<<gridN, TB>>>(pSrcC, pDstC);
    prep_w_kernel<<<4, TB>>>(W1, W2, Wn1, Wn2, pWt);
    hist_kernel<<<gridE, TB>>>(src, dst, pSrcC, pDstC);
    norm_kernel<<<gridN, TB>>>(pSrcC, pDstC, pOutN, pInN);
    scan1_kernel<<<SCAN_GRID, SCAN_BLK>>>(pDstC, pExcl, pBlk);
    scan2_kernel<<<1, 1024>>>(pBlk);
    scan3_kernel<<<SCAN_GRID, SCAN_BLK>>>(pExcl, pBlk, pRow, pCur);
    fill_kernel<<<gridE, TB>>>(src, dst, pCur, pEsrc);

    // ---- conv1 ----
    agg_kernel<<<gridAggW, TB>>>(node_feat, pRow, pEsrc, pOutN, pInN, pA, nullptr, nullptr);
    zero_stats_kernel<<<1, 256>>>(pStats);
    gemm_mma_kernel<<<GEMM_GRID, TB, SM_TOTAL>>>(pA, pWt + 0 * 16384, pWt + 1 * 16384, b1, pB, 0, pStats);
    sb_kernel<<<1, 128>>>(pStats, g1, be1, pScale, pBias);

    // ---- conv2 (BN1+lrelu fused into gather) ----
    agg_kernel<<<gridAggW, TB>>>(pB, pRow, pEsrc, pOutN, pInN, pA, pScale, pBias);
    zero_stats_kernel<<<1, 256>>>(pStats);
    gemm_mma_kernel<<<GEMM_GRID, TB, SM_TOTAL>>>(pA, pWt + 2 * 16384, pWt + 3 * 16384, b2, pB, 0, pStats);
    sb_kernel<<<1, 128>>>(pStats, g2, be2, pScale, pBias);

    // ---- convnode1 (BN2+lrelu fused into gather; act fused into gemm) ----
    agg_kernel<<<gridAggW, TB>>>(pB, pRow, pEsrc, pOutN, pInN, pA, pScale, pBias);
    gemm_mma_kernel<<<GEMM_GRID, TB, SM_TOTAL>>>(pA, pWt + 4 * 16384, pWt + 5 * 16384, bn1, pB, 1, nullptr);

    // ---- convnode2 ----
    agg_kernel<<<gridAggW, TB>>>(pB, pRow, pEsrc, pOutN, pInN, pA, nullptr, nullptr);
    gemm_mma_kernel<<<GEMM_GRID, TB, SM_TOTAL>>>(pA, pWt + 6 * 16384, pWt + 7 * 16384, bn2, pB, 1, nullptr);

    // ---- classifier ----
    final_kernel<<<gridFinal, TB>>>(pB, Wc, bc, out);
}